// round 5
// baseline (speedup 1.0000x reference)
#include <cuda_runtime.h>
#include <cuda_fp16.h>

// ---------------- problem constants ----------------
#define N_NODES   300000
#define NUM_USERS 200000
#define EMB       64
#define NNZ_E     5000000
#define ROW_U4    (EMB / 8)                  // 8 uint4 (16B) per fp16 row
#define NB_SCAN   ((N_NODES + 1023) / 1024)  // 293
#define VAL_SCALE 8191.0f
#define VAL_INV   (1.0f / 8191.0f)

// ---------------- device scratch (static; no allocations allowed) ----------------
__device__ uint4    g_t0[N_NODES * ROW_U4];   // fp16 tables (128B/row)
__device__ uint4    g_t1[N_NODES * ROW_U4];
__device__ uint4    g_t2[N_NODES * ROW_U4];
__device__ int      g_cnt[N_NODES];
__device__ int      g_scan[N_NODES];
__device__ int      g_rowptr[N_NODES];
__device__ int      g_rowend[N_NODES];
__device__ int      g_cursor[N_NODES];
__device__ unsigned g_edge[NNZ_E];            // col(19b) | val13(13b)<<19
__device__ int      g_bsum[512];
__device__ int      g_boff[512];

// ---------------- helpers ----------------
__device__ __forceinline__ unsigned pack_h2(float a, float b) {
    __half2 h = __floats2half2_rn(a, b);
    return *(unsigned*)&h;
}
__device__ __forceinline__ float2 unpack_h2(unsigned u) {
    return __half22float2(*(__half2*)&u);
}
__device__ __forceinline__ void acc_add(float* a, uint4 q, float v) {
    float2 f;
    f = unpack_h2(q.x); a[0] = fmaf(v, f.x, a[0]); a[1] = fmaf(v, f.y, a[1]);
    f = unpack_h2(q.y); a[2] = fmaf(v, f.x, a[2]); a[3] = fmaf(v, f.y, a[3]);
    f = unpack_h2(q.z); a[4] = fmaf(v, f.x, a[4]); a[5] = fmaf(v, f.y, a[5]);
    f = unpack_h2(q.w); a[6] = fmaf(v, f.x, a[6]); a[7] = fmaf(v, f.y, a[7]);
}

// ---------------- init: ego(fp32) -> g_t0 (fp16), plus zero g_cnt ----------------
__global__ void k_init16(const float4* __restrict__ ue,
                         const float4* __restrict__ ie) {
    int i = blockIdx.x * blockDim.x + threadIdx.x;
    if (i < N_NODES) g_cnt[i] = 0;           // fused counter zeroing
    if (i >= N_NODES * ROW_U4) return;
    float4 a, b;
    if (i < NUM_USERS * ROW_U4) {
        a = ue[i * 2]; b = ue[i * 2 + 1];
    } else {
        int j = i - NUM_USERS * ROW_U4;
        a = ie[j * 2]; b = ie[j * 2 + 1];
    }
    uint4 o;
    o.x = pack_h2(a.x, a.y); o.y = pack_h2(a.z, a.w);
    o.z = pack_h2(b.x, b.y); o.w = pack_h2(b.z, b.w);
    g_t0[i] = o;
}

// 4 edges per thread
__global__ void k_hist(const int4* __restrict__ row4) {
    int t = blockIdx.x * blockDim.x + threadIdx.x;
    if (t >= NNZ_E / 4) return;
    int4 r = __ldg(&row4[t]);
    atomicAdd(&g_cnt[r.x], 1);
    atomicAdd(&g_cnt[r.y], 1);
    atomicAdd(&g_cnt[r.z], 1);
    atomicAdd(&g_cnt[r.w], 1);
}

// ---- 2-level exclusive scan of g_cnt -> g_rowptr ----
__global__ void k_scan1() {
    __shared__ int sh[1024];
    int tid = threadIdx.x;
    int i = blockIdx.x * 1024 + tid;
    int v = (i < N_NODES) ? g_cnt[i] : 0;
    sh[tid] = v;
    for (int off = 1; off < 1024; off <<= 1) {
        __syncthreads();
        int t = (tid >= off) ? sh[tid - off] : 0;
        __syncthreads();
        sh[tid] += t;
    }
    if (i < N_NODES) g_scan[i] = sh[tid];
    if (tid == 1023) g_bsum[blockIdx.x] = sh[1023];
}

__global__ void k_scan2() {
    __shared__ int sh[512];
    int tid = threadIdx.x;
    int v = (tid < NB_SCAN) ? g_bsum[tid] : 0;
    sh[tid] = v;
    for (int off = 1; off < 512; off <<= 1) {
        __syncthreads();
        int t = (tid >= off) ? sh[tid - off] : 0;
        __syncthreads();
        sh[tid] += t;
    }
    if (tid < NB_SCAN) g_boff[tid] = sh[tid] - v;  // exclusive
}

__global__ void k_scan3() {
    int i = blockIdx.x * blockDim.x + threadIdx.x;
    if (i >= N_NODES) return;
    int c = g_cnt[i];
    int excl = g_scan[i] - c + g_boff[i >> 10];
    g_rowptr[i] = excl;
    g_cursor[i] = excl;
    g_rowend[i] = excl + c;
}

// 4 edges per thread; pack col+val13 into 4B
__global__ void k_scatter(const int4* __restrict__ row4,
                          const int4* __restrict__ col4,
                          const float4* __restrict__ val4) {
    int t = blockIdx.x * blockDim.x + threadIdx.x;
    if (t >= NNZ_E / 4) return;
    int4   r = __ldg(&row4[t]);
    int4   c = __ldg(&col4[t]);
    float4 v = __ldg(&val4[t]);
    unsigned q;
    int p;
    q = (unsigned)c.x | (__float2uint_rn(v.x * VAL_SCALE) << 19);
    p = atomicAdd(&g_cursor[r.x], 1); g_edge[p] = q;
    q = (unsigned)c.y | (__float2uint_rn(v.y * VAL_SCALE) << 19);
    p = atomicAdd(&g_cursor[r.y], 1); g_edge[p] = q;
    q = (unsigned)c.z | (__float2uint_rn(v.z * VAL_SCALE) << 19);
    p = atomicAdd(&g_cursor[r.z], 1); g_edge[p] = q;
    q = (unsigned)c.w | (__float2uint_rn(v.w * VAL_SCALE) << 19);
    p = atomicAdd(&g_cursor[r.w], 1); g_edge[p] = q;
}

// ---------------- SpMM inner loop: unroll-4, batched loads for MLP ----------------
__device__ __forceinline__ void spmm_row(const uint4* __restrict__ tin,
                                          int s, int e, int lane, float* acc) {
    int i = s;
    for (; i + 3 < e; i += 4) {
        unsigned p0 = __ldg(&g_edge[i]);
        unsigned p1 = __ldg(&g_edge[i + 1]);
        unsigned p2 = __ldg(&g_edge[i + 2]);
        unsigned p3 = __ldg(&g_edge[i + 3]);
        uint4 q0 = __ldg(&tin[((p0 & 0x7FFFFu) << 3) + lane]);
        uint4 q1 = __ldg(&tin[((p1 & 0x7FFFFu) << 3) + lane]);
        uint4 q2 = __ldg(&tin[((p2 & 0x7FFFFu) << 3) + lane]);
        uint4 q3 = __ldg(&tin[((p3 & 0x7FFFFu) << 3) + lane]);
        acc_add(acc, q0, (float)(p0 >> 19) * VAL_INV);
        acc_add(acc, q1, (float)(p1 >> 19) * VAL_INV);
        acc_add(acc, q2, (float)(p2 >> 19) * VAL_INV);
        acc_add(acc, q3, (float)(p3 >> 19) * VAL_INV);
    }
    for (; i < e; i++) {
        unsigned p0 = __ldg(&g_edge[i]);
        uint4 q0 = __ldg(&tin[((p0 & 0x7FFFFu) << 3) + lane]);
        acc_add(acc, q0, (float)(p0 >> 19) * VAL_INV);
    }
}

__global__ void __launch_bounds__(256)
k_spmm16(int stage) {
    const uint4* tin  = (stage == 0) ? g_t0 : g_t1;
    uint4*       tout = (stage == 0) ? g_t1 : g_t2;

    int g = blockIdx.x * blockDim.x + threadIdx.x;
    int r = g >> 3;
    if (r >= N_NODES) return;
    int lane = g & 7;

    float acc[8] = {0.f, 0.f, 0.f, 0.f, 0.f, 0.f, 0.f, 0.f};
    spmm_row(tin, g_rowptr[r], g_rowend[r], lane, acc);

    uint4 o;
    o.x = pack_h2(acc[0], acc[1]);
    o.y = pack_h2(acc[2], acc[3]);
    o.z = pack_h2(acc[4], acc[5]);
    o.w = pack_h2(acc[6], acc[7]);
    tout[(r << 3) + lane] = o;
}

// ---------------- SpMM stage 2 fused with combine ----------------
// out = (t0 + t1 + t2 + h3) / 4, h3 in fp32 registers (never quantized)
__global__ void __launch_bounds__(256)
k_spmm_final(float4* __restrict__ out) {
    int g = blockIdx.x * blockDim.x + threadIdx.x;
    int r = g >> 3;
    if (r >= N_NODES) return;
    int lane = g & 7;

    float acc[8] = {0.f, 0.f, 0.f, 0.f, 0.f, 0.f, 0.f, 0.f};
    spmm_row(g_t2, g_rowptr[r], g_rowend[r], lane, acc);

    int idx = (r << 3) + lane;
    uint4 a = __ldg(&g_t0[idx]);
    uint4 b = __ldg(&g_t1[idx]);
    uint4 c = __ldg(&g_t2[idx]);
    acc_add(acc, a, 1.0f);
    acc_add(acc, b, 1.0f);
    acc_add(acc, c, 1.0f);

    float4 o0 = make_float4(acc[0] * 0.25f, acc[1] * 0.25f,
                            acc[2] * 0.25f, acc[3] * 0.25f);
    float4 o1 = make_float4(acc[4] * 0.25f, acc[5] * 0.25f,
                            acc[6] * 0.25f, acc[7] * 0.25f);
    int fo = (r << 4) + (lane << 1);
    __stcs(&out[fo], o0);
    __stcs(&out[fo + 1], o1);
}

// ---------------- launch ----------------
extern "C" void kernel_launch(void* const* d_in, const int* in_sizes, int n_in,
                              void* d_out, int out_size) {
    const float* user_emb = (const float*)d_in[0];
    const float* item_emb = (const float*)d_in[1];
    const int*   edge_row = (const int*)  d_in[2];
    const int*   edge_col = (const int*)  d_in[3];
    const float* edge_val = (const float*)d_in[4];
    float*       out      = (float*)d_out;

    const int TB = 256;
    const int gInit  = (N_NODES * ROW_U4 + TB - 1) / TB;
    const int gNode  = (N_NODES + TB - 1) / TB;
    const int gEdge4 = (NNZ_E / 4 + TB - 1) / TB;
    const int gSpmm  = (N_NODES * 8 + TB - 1) / TB;

    k_init16<<<gInit, TB>>>((const float4*)user_emb, (const float4*)item_emb);
    k_hist<<<gEdge4, TB>>>((const int4*)edge_row);
    k_scan1<<<NB_SCAN, 1024>>>();
    k_scan2<<<1, 512>>>();
    k_scan3<<<gNode, TB>>>();
    k_scatter<<<gEdge4, TB>>>((const int4*)edge_row, (const int4*)edge_col,
                              (const float4*)edge_val);

    k_spmm16<<<gSpmm, TB>>>(0);                 // t0 -> t1
    k_spmm16<<<gSpmm, TB>>>(1);                 // t1 -> t2
    k_spmm_final<<<gSpmm, TB>>>((float4*)out);  // t2 -> out (fused combine)
}

// round 6
// speedup vs baseline: 1.0221x; 1.0221x over previous
#include <cuda_runtime.h>
#include <cuda_fp16.h>

// ---------------- problem constants ----------------
#define N_NODES   300000
#define NUM_USERS 200000
#define EMB       64
#define NNZ_E     5000000
#define ROW_U4    (EMB / 8)                  // 8 uint4 (16B) per fp16 row
#define NB_SCAN   ((N_NODES + 1023) / 1024)  // 293
#define VAL_SCALE 8191.0f
#define VAL_INV   (1.0f / 8191.0f)

// ---------------- device scratch (static; no allocations allowed) ----------------
__device__ uint4              g_t0[N_NODES * ROW_U4];   // fp16 tables (128B/row)
__device__ uint4              g_t1[N_NODES * ROW_U4];
__device__ uint4              g_t2[N_NODES * ROW_U4];
__device__ int                g_cnt[N_NODES];
__device__ int2               g_rowse[N_NODES];         // (start, end)
__device__ int                g_cursor[N_NODES];
__device__ unsigned           g_edge[NNZ_E];            // col(19b) | val13<<19
__device__ unsigned long long g_state[NB_SCAN];         // flag<<32 | sum

// ---------------- helpers ----------------
__device__ __forceinline__ unsigned pack_h2(float a, float b) {
    __half2 h = __floats2half2_rn(a, b);
    return *(unsigned*)&h;
}
__device__ __forceinline__ float2 unpack_h2(unsigned u) {
    return __half22float2(*(__half2*)&u);
}
__device__ __forceinline__ void acc_add(float* a, uint4 q, float v) {
    float2 f;
    f = unpack_h2(q.x); a[0] = fmaf(v, f.x, a[0]); a[1] = fmaf(v, f.y, a[1]);
    f = unpack_h2(q.y); a[2] = fmaf(v, f.x, a[2]); a[3] = fmaf(v, f.y, a[3]);
    f = unpack_h2(q.z); a[4] = fmaf(v, f.x, a[4]); a[5] = fmaf(v, f.y, a[5]);
    f = unpack_h2(q.w); a[6] = fmaf(v, f.x, a[6]); a[7] = fmaf(v, f.y, a[7]);
}

// ---------------- init: ego(fp32) -> g_t0 (fp16), zero cnt + scan state ----------------
__global__ void k_init16(const float4* __restrict__ ue,
                         const float4* __restrict__ ie) {
    int i = blockIdx.x * blockDim.x + threadIdx.x;
    if (i < N_NODES) g_cnt[i] = 0;
    if (i < NB_SCAN) g_state[i] = 0ULL;
    if (i >= N_NODES * ROW_U4) return;
    float4 a, b;
    if (i < NUM_USERS * ROW_U4) {
        a = ue[i * 2]; b = ue[i * 2 + 1];
    } else {
        int j = i - NUM_USERS * ROW_U4;
        a = ie[j * 2]; b = ie[j * 2 + 1];
    }
    uint4 o;
    o.x = pack_h2(a.x, a.y); o.y = pack_h2(a.z, a.w);
    o.z = pack_h2(b.x, b.y); o.w = pack_h2(b.z, b.w);
    g_t0[i] = o;
}

// 4 edges per thread
__global__ void k_hist(const int4* __restrict__ row4) {
    int t = blockIdx.x * blockDim.x + threadIdx.x;
    if (t >= NNZ_E / 4) return;
    int4 r = __ldg(&row4[t]);
    atomicAdd(&g_cnt[r.x], 1);
    atomicAdd(&g_cnt[r.y], 1);
    atomicAdd(&g_cnt[r.z], 1);
    atomicAdd(&g_cnt[r.w], 1);
}

// ---------------- single-pass scan with decoupled lookback ----------------
// Produces g_rowse (start,end) and g_cursor. All 293 blocks co-resident.
__global__ void __launch_bounds__(1024)
k_scan_lb() {
    __shared__ int sh[1024];
    __shared__ int s_prefix;
    int tid = threadIdx.x;
    int bid = blockIdx.x;
    int i = bid * 1024 + tid;
    int v = (i < N_NODES) ? g_cnt[i] : 0;

    // inclusive scan in smem
    sh[tid] = v;
    for (int off = 1; off < 1024; off <<= 1) {
        __syncthreads();
        int t = (tid >= off) ? sh[tid - off] : 0;
        __syncthreads();
        sh[tid] += t;
    }
    int incl = sh[tid];
    __syncthreads();
    int agg = sh[1023];

    // publish aggregate (block 0 publishes prefix immediately)
    if (tid == 1023) {
        unsigned long long pkt =
            ((bid == 0 ? 2ULL : 1ULL) << 32) | (unsigned)agg;
        atomicExch(&g_state[bid], pkt);
    }
    if (tid == 0) s_prefix = 0;

    // warp 0: decoupled lookback
    if (bid > 0 && tid < 32) {
        int exc = 0;
        int j = bid - 1;
        while (true) {
            int idx = j - tid;
            unsigned long long pkt = 0;
            if (idx >= 0) {
                do { pkt = atomicAdd(&g_state[idx], 0ULL); }
                while (!(pkt >> 32));
            }
            unsigned flag = (idx >= 0) ? (unsigned)(pkt >> 32) : 0u;
            int val = (int)(unsigned)(pkt & 0xffffffffu);
            unsigned ball = __ballot_sync(0xffffffffu, flag == 2u);
            if (ball) {
                int fp = __ffs(ball) - 1;
                int contrib = (tid <= fp && idx >= 0) ? val : 0;
                exc += __reduce_add_sync(0xffffffffu, contrib);
                break;
            } else {
                int contrib = (idx >= 0) ? val : 0;
                exc += __reduce_add_sync(0xffffffffu, contrib);
                j -= 32;
                if (j < 0) break;   // safety (block 0 always has flag 2)
            }
        }
        if (tid == 0) {
            s_prefix = exc;
            atomicExch(&g_state[bid],
                       (2ULL << 32) | (unsigned)(exc + agg));
        }
    }
    __syncthreads();

    if (i < N_NODES) {
        int base = s_prefix;
        int rend = base + incl;
        int rp = rend - v;
        g_rowse[i] = make_int2(rp, rend);
        g_cursor[i] = rp;
    }
}

// 4 edges per thread; pack col+val13 into 4B
__global__ void k_scatter(const int4* __restrict__ row4,
                          const int4* __restrict__ col4,
                          const float4* __restrict__ val4) {
    int t = blockIdx.x * blockDim.x + threadIdx.x;
    if (t >= NNZ_E / 4) return;
    int4   r = __ldg(&row4[t]);
    int4   c = __ldg(&col4[t]);
    float4 v = __ldg(&val4[t]);
    unsigned q;
    int p;
    q = (unsigned)c.x | (__float2uint_rn(v.x * VAL_SCALE) << 19);
    p = atomicAdd(&g_cursor[r.x], 1); g_edge[p] = q;
    q = (unsigned)c.y | (__float2uint_rn(v.y * VAL_SCALE) << 19);
    p = atomicAdd(&g_cursor[r.y], 1); g_edge[p] = q;
    q = (unsigned)c.z | (__float2uint_rn(v.z * VAL_SCALE) << 19);
    p = atomicAdd(&g_cursor[r.z], 1); g_edge[p] = q;
    q = (unsigned)c.w | (__float2uint_rn(v.w * VAL_SCALE) << 19);
    p = atomicAdd(&g_cursor[r.w], 1); g_edge[p] = q;
}

// ---------------- SpMM inner loop (unroll-2; LTS-bound, more MLP doesn't help) ----------------
__device__ __forceinline__ void spmm_row(const uint4* __restrict__ tin,
                                          int s, int e, int lane, float* acc) {
    int i = s;
    for (; i + 1 < e; i += 2) {
        unsigned p0 = __ldg(&g_edge[i]);
        unsigned p1 = __ldg(&g_edge[i + 1]);
        uint4 q0 = __ldg(&tin[((p0 & 0x7FFFFu) << 3) + lane]);
        uint4 q1 = __ldg(&tin[((p1 & 0x7FFFFu) << 3) + lane]);
        acc_add(acc, q0, (float)(p0 >> 19) * VAL_INV);
        acc_add(acc, q1, (float)(p1 >> 19) * VAL_INV);
    }
    if (i < e) {
        unsigned p0 = __ldg(&g_edge[i]);
        uint4 q0 = __ldg(&tin[((p0 & 0x7FFFFu) << 3) + lane]);
        acc_add(acc, q0, (float)(p0 >> 19) * VAL_INV);
    }
}

__global__ void __launch_bounds__(256)
k_spmm16(int stage) {
    const uint4* tin  = (stage == 0) ? g_t0 : g_t1;
    uint4*       tout = (stage == 0) ? g_t1 : g_t2;

    int g = blockIdx.x * blockDim.x + threadIdx.x;
    int r = g >> 3;
    if (r >= N_NODES) return;
    int lane = g & 7;

    int2 se = __ldg(&g_rowse[r]);
    float acc[8] = {0.f, 0.f, 0.f, 0.f, 0.f, 0.f, 0.f, 0.f};
    spmm_row(tin, se.x, se.y, lane, acc);

    uint4 o;
    o.x = pack_h2(acc[0], acc[1]);
    o.y = pack_h2(acc[2], acc[3]);
    o.z = pack_h2(acc[4], acc[5]);
    o.w = pack_h2(acc[6], acc[7]);
    tout[(r << 3) + lane] = o;
}

// ---------------- SpMM stage 2 fused with combine ----------------
// out = (t0 + t1 + t2 + h3) / 4, h3 in fp32 registers (never quantized)
__global__ void __launch_bounds__(256)
k_spmm_final(float4* __restrict__ out) {
    int g = blockIdx.x * blockDim.x + threadIdx.x;
    int r = g >> 3;
    if (r >= N_NODES) return;
    int lane = g & 7;

    int2 se = __ldg(&g_rowse[r]);
    float acc[8] = {0.f, 0.f, 0.f, 0.f, 0.f, 0.f, 0.f, 0.f};
    spmm_row(g_t2, se.x, se.y, lane, acc);

    int idx = (r << 3) + lane;
    uint4 a = __ldg(&g_t0[idx]);
    uint4 b = __ldg(&g_t1[idx]);
    uint4 c = __ldg(&g_t2[idx]);
    acc_add(acc, a, 1.0f);
    acc_add(acc, b, 1.0f);
    acc_add(acc, c, 1.0f);

    float4 o0 = make_float4(acc[0] * 0.25f, acc[1] * 0.25f,
                            acc[2] * 0.25f, acc[3] * 0.25f);
    float4 o1 = make_float4(acc[4] * 0.25f, acc[5] * 0.25f,
                            acc[6] * 0.25f, acc[7] * 0.25f);
    int fo = (r << 4) + (lane << 1);
    __stcs(&out[fo], o0);
    __stcs(&out[fo + 1], o1);
}

// ---------------- launch ----------------
extern "C" void kernel_launch(void* const* d_in, const int* in_sizes, int n_in,
                              void* d_out, int out_size) {
    const float* user_emb = (const float*)d_in[0];
    const float* item_emb = (const float*)d_in[1];
    const int*   edge_row = (const int*)  d_in[2];
    const int*   edge_col = (const int*)  d_in[3];
    const float* edge_val = (const float*)d_in[4];
    float*       out      = (float*)d_out;

    const int TB = 256;
    const int gInit  = (N_NODES * ROW_U4 + TB - 1) / TB;
    const int gEdge4 = (NNZ_E / 4 + TB - 1) / TB;
    const int gSpmm  = (N_NODES * 8 + TB - 1) / TB;

    k_init16<<<gInit, TB>>>((const float4*)user_emb, (const float4*)item_emb);
    k_hist<<<gEdge4, TB>>>((const int4*)edge_row);
    k_scan_lb<<<NB_SCAN, 1024>>>();
    k_scatter<<<gEdge4, TB>>>((const int4*)edge_row, (const int4*)edge_col,
                              (const float4*)edge_val);

    k_spmm16<<<gSpmm, TB>>>(0);                 // t0 -> t1
    k_spmm16<<<gSpmm, TB>>>(1);                 // t1 -> t2
    k_spmm_final<<<gSpmm, TB>>>((float4*)out);  // t2 -> out (fused combine)
}